// round 15
// baseline (speedup 1.0000x reference)
#include <cuda_runtime.h>
#include <math.h>
#include <stdint.h>

#define FULL 0xffffffffu

// ---------------- problem constants ----------------
constexpr int DIM   = 256;
constexpr int HEADS = 8;
constexpr float SCALE_L2E = 0.17677669529663687f * 1.4426950408889634f;

constexpr int NX  = 6400;
constexpr int NY  = 1024;
constexpr int BY  = 4;
constexpr int NRX = 1600;
constexpr int NRY = 256;
constexpr int MQ  = NX + BY * NY;      // 10496
constexpr int MR  = NRX + BY * NRY;    // 2624
constexpr int XBLK2 = NX / 128;        // 50
constexpr int YBLK2 = NY / 128;        // 8

// ---------------- scratch (device globals) ----------------
__device__ float g_q   [MQ * DIM];
__device__ float g_o   [MQ * DIM];
__device__ float g_red [MR * DIM];
__device__ float g_kv  [MR * 2 * DIM];
__device__ float g_kvym[NRY * 2 * DIM];
__device__ float g_srwT[1024 * DIM];

// ---------------- tf32 helpers ----------------
__device__ __forceinline__ uint32_t to_tf32(float f) {
    uint32_t r; asm("cvt.rna.tf32.f32 %0, %1;" : "=r"(r) : "f"(f)); return r;
}
__device__ __forceinline__ uint4 cvt4(uint4 v) {
    uint4 r;
    r.x = to_tf32(__uint_as_float(v.x));
    r.y = to_tf32(__uint_as_float(v.y));
    r.z = to_tf32(__uint_as_float(v.z));
    r.w = to_tf32(__uint_as_float(v.w));
    return r;
}
__device__ __forceinline__ void mma_tf32(float* d, const uint32_t* a, const uint32_t* b,
                                         const float* c)
{
    asm volatile(
        "mma.sync.aligned.m16n8k8.row.col.f32.tf32.tf32.f32 "
        "{%0,%1,%2,%3}, {%4,%5,%6,%7}, {%8,%9}, {%10,%11,%12,%13};"
        : "=f"(d[0]), "=f"(d[1]), "=f"(d[2]), "=f"(d[3])
        : "r"(a[0]), "r"(a[1]), "r"(a[2]), "r"(a[3]),
          "r"(b[0]), "r"(b[1]),
          "f"(c[0]), "f"(c[1]), "f"(c[2]), "f"(c[3]));
}
__device__ __forceinline__ float ex2(float x) {
    float r; asm("ex2.approx.f32 %0, %1;" : "=f"(r) : "f"(x)); return r;
}
__device__ __forceinline__ void cp_async16(uint32_t dst, const void* src) {
    asm volatile("cp.async.cg.shared.global [%0], [%1], 16;" :: "r"(dst), "l"(src));
}

// ---------------- weight transpose ----------------
__global__ void transpose_w_kernel(const float* __restrict__ srw, float* __restrict__ wT)
{
    int idx = blockIdx.x * 256 + threadIdx.x;
    int o = idx >> 10;
    int k = idx & 1023;
    wT[k * 256 + o] = srw[idx];
}

constexpr int ASTR = 36;
constexpr int BSTR = 72;

// ============ tf32 MMA GEMM, 64x64 tile (KV proj; optional tf32-rounded output) ============
__global__ void __launch_bounds__(256) mma_gemm_kernel(
    const float* __restrict__ A1, const float* __restrict__ A2, int rowSplit,
    const float* __restrict__ B, const float* __restrict__ bias,
    float* __restrict__ C, int M, int N, int K, int roundC)
{
    __shared__ uint32_t As[2][64][ASTR];
    __shared__ uint32_t Bs[2][32][BSTR];

    const int tid  = threadIdx.x;
    const int wid  = tid >> 5;
    const int lane = tid & 31;
    const int gid  = lane >> 2;
    const int tig  = lane & 3;
    const int w16  = (wid >> 1) * 16;
    const int c32  = (wid & 1) * 32;
    const int rowBase = blockIdx.y * 64;
    const int colBase = blockIdx.x * 64;

    const float* aPtr[2];
    int aR[2], aC[2];
    #pragma unroll
    for (int it = 0; it < 2; it++) {
        int e  = tid + it * 256;
        aR[it] = e >> 3;
        aC[it] = (e & 7) * 4;
        int m  = rowBase + aR[it];
        aPtr[it] = (m < rowSplit) ? (A1 + (size_t)m * K)
                                  : (A2 + (size_t)(m - rowSplit) * K);
    }
    const float* bPtr[2];
    int bR[2], bC[2];
    #pragma unroll
    for (int it = 0; it < 2; it++) {
        int e  = tid + it * 256;
        bR[it] = e >> 4;
        bC[it] = (e & 15) * 4;
        bPtr[it] = B + (size_t)bR[it] * N + colBase + bC[it];
    }

    float acc[4][4];
    #pragma unroll
    for (int n = 0; n < 4; n++)
        #pragma unroll
        for (int r = 0; r < 4; r++) acc[n][r] = 0.f;

    const int nChunks = K >> 5;
    uint4 aReg[2], bReg[2];

    #pragma unroll
    for (int it = 0; it < 2; it++) {
        aReg[it] = *(const uint4*)&aPtr[it][aC[it]];
        bReg[it] = *(const uint4*)&bPtr[it][0];
    }
    #pragma unroll
    for (int it = 0; it < 2; it++) {
        *(uint4*)&As[0][aR[it]][aC[it]] = cvt4(aReg[it]);
        *(uint4*)&Bs[0][bR[it]][bC[it]] = cvt4(bReg[it]);
    }

    for (int c = 0; c < nChunks; c++) {
        const int cur = c & 1;
        __syncthreads();
        if (c + 1 < nChunks) {
            int k0 = (c + 1) << 5;
            #pragma unroll
            for (int it = 0; it < 2; it++) {
                aReg[it] = *(const uint4*)&aPtr[it][k0 + aC[it]];
                bReg[it] = *(const uint4*)&bPtr[it][(size_t)k0 * N];
            }
        }

        #pragma unroll
        for (int ks = 0; ks < 4; ks++) {
            uint32_t af[4];
            af[0] = As[cur][w16 + gid][ks * 8 + tig];
            af[1] = As[cur][w16 + gid + 8][ks * 8 + tig];
            af[2] = As[cur][w16 + gid][ks * 8 + tig + 4];
            af[3] = As[cur][w16 + gid + 8][ks * 8 + tig + 4];
            #pragma unroll
            for (int n = 0; n < 4; n++) {
                uint32_t bf[2];
                bf[0] = Bs[cur][ks * 8 + tig][c32 + n * 8 + gid];
                bf[1] = Bs[cur][ks * 8 + tig + 4][c32 + n * 8 + gid];
                mma_tf32(acc[n], af, bf, acc[n]);
            }
        }

        if (c + 1 < nChunks) {
            const int nxt = cur ^ 1;
            #pragma unroll
            for (int it = 0; it < 2; it++) {
                *(uint4*)&As[nxt][aR[it]][aC[it]] = cvt4(aReg[it]);
                *(uint4*)&Bs[nxt][bR[it]][bC[it]] = cvt4(bReg[it]);
            }
        }
    }

    const size_t rlo = (size_t)(rowBase + w16 + gid) * N;
    const size_t rhi = (size_t)(rowBase + w16 + gid + 8) * N;
    #pragma unroll
    for (int n = 0; n < 4; n++) {
        int col = colBase + c32 + n * 8 + 2 * tig;
        float b0 = bias ? bias[col]     : 0.f;
        float b1 = bias ? bias[col + 1] : 0.f;
        float v00 = acc[n][0] + b0, v01 = acc[n][1] + b1;
        float v10 = acc[n][2] + b0, v11 = acc[n][3] + b1;
        if (roundC) {
            v00 = __uint_as_float(to_tf32(v00));
            v01 = __uint_as_float(to_tf32(v01));
            v10 = __uint_as_float(to_tf32(v10));
            v11 = __uint_as_float(to_tf32(v11));
        }
        *(float2*)&C[rlo + col] = make_float2(v00, v01);
        *(float2*)&C[rhi + col] = make_float2(v10, v11);
    }
}

// ============ tf32 MMA GEMM, 128x64 tile, dynamic smem (Q proj / out proj) ============
__global__ void __launch_bounds__(256) mma_gemm128_kernel(
    const float* __restrict__ A1, const float* __restrict__ A2, int rowSplit,
    const float* __restrict__ B, const float* __restrict__ bias,
    float* __restrict__ C, int M, int N, int K)
{
    extern __shared__ uint32_t smemBuf[];
    auto As = (uint32_t(*)[128][ASTR]) smemBuf;
    auto Bs = (uint32_t(*)[32][BSTR]) (smemBuf + 2 * 128 * ASTR);

    const int tid  = threadIdx.x;
    const int wid  = tid >> 5;
    const int lane = tid & 31;
    const int gid  = lane >> 2;
    const int tig  = lane & 3;
    const int r32  = (wid >> 1) * 32;
    const int c32  = (wid & 1) * 32;
    const int rowBase = blockIdx.y * 128;
    const int colBase = blockIdx.x * 64;

    const float* aPtr[4];
    int aR[4], aC[4];
    #pragma unroll
    for (int it = 0; it < 4; it++) {
        int e  = tid + it * 256;
        aR[it] = e >> 3;
        aC[it] = (e & 7) * 4;
        int m  = rowBase + aR[it];
        aPtr[it] = (m < rowSplit) ? (A1 + (size_t)m * K)
                                  : (A2 + (size_t)(m - rowSplit) * K);
    }
    const float* bPtr[2];
    int bR[2], bC[2];
    #pragma unroll
    for (int it = 0; it < 2; it++) {
        int e  = tid + it * 256;
        bR[it] = e >> 4;
        bC[it] = (e & 15) * 4;
        bPtr[it] = B + (size_t)bR[it] * N + colBase + bC[it];
    }

    float acc[2][4][4];
    #pragma unroll
    for (int m = 0; m < 2; m++)
        #pragma unroll
        for (int n = 0; n < 4; n++)
            #pragma unroll
            for (int r = 0; r < 4; r++) acc[m][n][r] = 0.f;

    const int nChunks = K >> 5;
    uint4 aReg[4], bReg[2];

    #pragma unroll
    for (int it = 0; it < 4; it++) aReg[it] = *(const uint4*)&aPtr[it][aC[it]];
    #pragma unroll
    for (int it = 0; it < 2; it++) bReg[it] = *(const uint4*)&bPtr[it][0];
    #pragma unroll
    for (int it = 0; it < 4; it++) *(uint4*)&As[0][aR[it]][aC[it]] = cvt4(aReg[it]);
    #pragma unroll
    for (int it = 0; it < 2; it++) *(uint4*)&Bs[0][bR[it]][bC[it]] = cvt4(bReg[it]);

    for (int c = 0; c < nChunks; c++) {
        const int cur = c & 1;
        __syncthreads();
        if (c + 1 < nChunks) {
            int k0 = (c + 1) << 5;
            #pragma unroll
            for (int it = 0; it < 4; it++) aReg[it] = *(const uint4*)&aPtr[it][k0 + aC[it]];
            #pragma unroll
            for (int it = 0; it < 2; it++) bReg[it] = *(const uint4*)&bPtr[it][(size_t)k0 * N];
        }

        #pragma unroll
        for (int ks = 0; ks < 4; ks++) {
            uint32_t af[2][4];
            #pragma unroll
            for (int m = 0; m < 2; m++) {
                int rb = r32 + m * 16;
                af[m][0] = As[cur][rb + gid][ks * 8 + tig];
                af[m][1] = As[cur][rb + gid + 8][ks * 8 + tig];
                af[m][2] = As[cur][rb + gid][ks * 8 + tig + 4];
                af[m][3] = As[cur][rb + gid + 8][ks * 8 + tig + 4];
            }
            #pragma unroll
            for (int n = 0; n < 4; n++) {
                uint32_t bf[2];
                bf[0] = Bs[cur][ks * 8 + tig][c32 + n * 8 + gid];
                bf[1] = Bs[cur][ks * 8 + tig + 4][c32 + n * 8 + gid];
                mma_tf32(acc[0][n], af[0], bf, acc[0][n]);
                mma_tf32(acc[1][n], af[1], bf, acc[1][n]);
            }
        }

        if (c + 1 < nChunks) {
            const int nxt = cur ^ 1;
            #pragma unroll
            for (int it = 0; it < 4; it++) *(uint4*)&As[nxt][aR[it]][aC[it]] = cvt4(aReg[it]);
            #pragma unroll
            for (int it = 0; it < 2; it++) *(uint4*)&Bs[nxt][bR[it]][bC[it]] = cvt4(bReg[it]);
        }
    }

    #pragma unroll
    for (int m = 0; m < 2; m++) {
        const size_t rlo = (size_t)(rowBase + r32 + m * 16 + gid) * N;
        const size_t rhi = (size_t)(rowBase + r32 + m * 16 + gid + 8) * N;
        #pragma unroll
        for (int n = 0; n < 4; n++) {
            int col = colBase + c32 + n * 8 + 2 * tig;
            float b0 = bias ? bias[col]     : 0.f;
            float b1 = bias ? bias[col + 1] : 0.f;
            *(float2*)&C[rlo + col] = make_float2(acc[m][n][0] + b0, acc[m][n][1] + b1);
            *(float2*)&C[rhi + col] = make_float2(acc[m][n][2] + b0, acc[m][n][3] + b1);
        }
    }
}

// ============ merged SR conv (x + y), tf32 MMA, double-buffered ============
__global__ void __launch_bounds__(256) mma_conv_kernel(
    const float* __restrict__ X1, const float* __restrict__ X2,
    const float* __restrict__ WT, const float* __restrict__ bias,
    float* __restrict__ C)
{
    __shared__ uint32_t As[2][64][ASTR];
    __shared__ uint32_t Bs[2][32][BSTR];

    const int tid  = threadIdx.x;
    const int wid  = tid >> 5;
    const int lane = tid & 31;
    const int gid  = lane >> 2;
    const int tig  = lane & 3;
    const int w16  = (wid >> 1) * 16;
    const int c32  = (wid & 1) * 32;
    const int rowBase = blockIdx.y * 64;
    const int colBase = blockIdx.x * 64;

    const float* aPtr[2];
    int aR[2], aSc[2], aIq[2];
    #pragma unroll
    for (int it = 0; it < 2; it++) {
        int e   = tid + it * 256;
        int r   = e >> 3;
        int sub = e & 7;
        int p   = sub & 3;
        int iq  = sub >> 2;
        int kh  = p >> 1, kw = p & 1;
        int m   = rowBase + r;
        const float* src;
        int mm, srcW;
        if (m < NRX) { src = X1; mm = m; srcW = 80; }
        else {
            int t = m - NRX;
            src = X2 + (size_t)(t / NRY) * NY * 256;
            mm  = t % NRY;
            srcW = 32;
        }
        int redW = srcW >> 1;
        int oh = mm / redW, ow = mm % redW;
        int tok = (oh * 2 + kh) * srcW + (ow * 2 + kw);
        aPtr[it] = src + (size_t)tok * 256;
        aR[it]  = r;
        aSc[it] = iq * 16 + p;
        aIq[it] = iq * 4;
    }
    const float* bPtr[2];
    int bR[2], bC[2];
    #pragma unroll
    for (int it = 0; it < 2; it++) {
        int e  = tid + it * 256;
        bR[it] = e >> 4;
        bC[it] = (e & 15) * 4;
        bPtr[it] = WT + (size_t)bR[it] * 256 + colBase + bC[it];
    }

    float acc[4][4];
    #pragma unroll
    for (int n = 0; n < 4; n++)
        #pragma unroll
        for (int r = 0; r < 4; r++) acc[n][r] = 0.f;

    const int nChunks = 32;
    float4 aReg[2];
    uint4  bReg[2];

    #pragma unroll
    for (int it = 0; it < 2; it++) {
        aReg[it] = *(const float4*)&aPtr[it][aIq[it]];
        bReg[it] = *(const uint4*)&bPtr[it][0];
    }
    #pragma unroll
    for (int it = 0; it < 2; it++) {
        int sc = aSc[it];
        As[0][aR[it]][sc + 0]  = to_tf32(aReg[it].x);
        As[0][aR[it]][sc + 4]  = to_tf32(aReg[it].y);
        As[0][aR[it]][sc + 8]  = to_tf32(aReg[it].z);
        As[0][aR[it]][sc + 12] = to_tf32(aReg[it].w);
        *(uint4*)&Bs[0][bR[it]][bC[it]] = cvt4(bReg[it]);
    }

    for (int c = 0; c < nChunks; c++) {
        const int cur = c & 1;
        __syncthreads();
        if (c + 1 < nChunks) {
            int i0 = ((c + 1) << 3);
            #pragma unroll
            for (int it = 0; it < 2; it++) {
                aReg[it] = *(const float4*)&aPtr[it][i0 + aIq[it]];
                bReg[it] = *(const uint4*)&bPtr[it][(size_t)((c + 1) << 5) * 256];
            }
        }

        #pragma unroll
        for (int ks = 0; ks < 4; ks++) {
            uint32_t af[4];
            af[0] = As[cur][w16 + gid][ks * 8 + tig];
            af[1] = As[cur][w16 + gid + 8][ks * 8 + tig];
            af[2] = As[cur][w16 + gid][ks * 8 + tig + 4];
            af[3] = As[cur][w16 + gid + 8][ks * 8 + tig + 4];
            #pragma unroll
            for (int n = 0; n < 4; n++) {
                uint32_t bf[2];
                bf[0] = Bs[cur][ks * 8 + tig][c32 + n * 8 + gid];
                bf[1] = Bs[cur][ks * 8 + tig + 4][c32 + n * 8 + gid];
                mma_tf32(acc[n], af, bf, acc[n]);
            }
        }

        if (c + 1 < nChunks) {
            const int nxt = cur ^ 1;
            #pragma unroll
            for (int it = 0; it < 2; it++) {
                int sc = aSc[it];
                As[nxt][aR[it]][sc + 0]  = to_tf32(aReg[it].x);
                As[nxt][aR[it]][sc + 4]  = to_tf32(aReg[it].y);
                As[nxt][aR[it]][sc + 8]  = to_tf32(aReg[it].z);
                As[nxt][aR[it]][sc + 12] = to_tf32(aReg[it].w);
                *(uint4*)&Bs[nxt][bR[it]][bC[it]] = cvt4(bReg[it]);
            }
        }
    }

    const size_t rlo = (size_t)(rowBase + w16 + gid) * 256;
    const size_t rhi = (size_t)(rowBase + w16 + gid + 8) * 256;
    #pragma unroll
    for (int n = 0; n < 4; n++) {
        int col = colBase + c32 + n * 8 + 2 * tig;
        float b0 = bias[col];
        float b1 = bias[col + 1];
        *(float2*)&C[rlo + col] = make_float2(acc[n][0] + b0, acc[n][1] + b1);
        *(float2*)&C[rhi + col] = make_float2(acc[n][2] + b0, acc[n][3] + b1);
    }
}

// ---------------- LayerNorm (in place) ----------------
__global__ void ln_kernel(float* __restrict__ red, const float* __restrict__ g,
                          const float* __restrict__ b)
{
    const int t = blockIdx.x;
    const int c = threadIdx.x;
    __shared__ float sh[8];
    __shared__ float s_mean, s_rstd;

    float v = red[(size_t)t * 256 + c];

    float x = v;
    #pragma unroll
    for (int o = 16; o > 0; o >>= 1) x += __shfl_xor_sync(FULL, x, o);
    if ((c & 31) == 0) sh[c >> 5] = x;
    __syncthreads();
    if (c == 0) {
        float s = 0.f;
        #pragma unroll
        for (int i = 0; i < 8; i++) s += sh[i];
        s_mean = s * (1.0f / 256.0f);
    }
    __syncthreads();

    float d = v - s_mean;
    float x2 = d * d;
    #pragma unroll
    for (int o = 16; o > 0; o >>= 1) x2 += __shfl_xor_sync(FULL, x2, o);
    if ((c & 31) == 0) sh[c >> 5] = x2;
    __syncthreads();
    if (c == 0) {
        float s = 0.f;
        #pragma unroll
        for (int i = 0; i < 8; i++) s += sh[i];
        s_rstd = rsqrtf(s * (1.0f / 256.0f) + 1e-5f);
    }
    __syncthreads();

    red[(size_t)t * 256 + c] = d * s_rstd * g[c] + b[c];
}

// ---------------- batch mean of support KV (tf32-rounded output) ----------------
__global__ void meankv_kernel(const float* __restrict__ kvy, float* __restrict__ out)
{
    int idx = blockIdx.x * 256 + threadIdx.x;
    const int STRIDE = NRY * 2 * DIM;
    float v = 0.25f * (kvy[idx] + kvy[idx + STRIDE] + kvy[idx + 2 * STRIDE] + kvy[idx + 3 * STRIDE]);
    out[idx] = __uint_as_float(to_tf32(v));
}

// ---------------- tf32 MMA flash attention: 128-query tiles, cp.async pipeline ----------------
// 256 threads / 8 warps; warp w owns q rows w*16..w*16+15 (identical per-warp math to R14).
constexpr int KSTR = 36;
constexpr int VSTR = 40;
constexpr int PSTR = 68;
constexpr int ATTN_SMEM = (2 * 64 * KSTR + 2 * 64 * VSTR + 128 * PSTR) * 4;  // 73728 B

__global__ void __launch_bounds__(256) attn_mma_kernel(
    const float* __restrict__ q_all, const float* __restrict__ KV1,
    const float* __restrict__ kvy, const float* __restrict__ kvym,
    float* __restrict__ o_all, int N1, int N2)
{
    extern __shared__ uint32_t dyn[];
    uint32_t* KsB = dyn;                                   // [2][64][KSTR]
    uint32_t* VsB = dyn + 2 * 64 * KSTR;                   // [2][64][VSTR]
    uint32_t* Ps  = dyn + 2 * 64 * KSTR + 2 * 64 * VSTR;   // [128][PSTR]
    const uint32_t smemBase = (uint32_t)__cvta_generic_to_shared(dyn);

    const int h  = blockIdx.y;
    const int bx = blockIdx.x;

    const float* Q;
    float*       O;
    const float* KV2;
    int q0;
    if (bx < XBLK2) {
        Q = q_all; O = o_all; KV2 = kvym; q0 = bx * 128;
    } else {
        int t  = bx - XBLK2;
        int bz = t >> 3;          // / YBLK2 (8)
        int qb = t & 7;
        size_t off = (size_t)(NX + bz * NY) * 256;
        Q = q_all + off; O = o_all + off;
        KV2 = kvy + (size_t)bz * NRY * 512;
        q0 = qb * 128;
    }

    const int tid  = threadIdx.x;
    const int wid  = tid >> 5;
    const int lane = tid & 31;
    const int gid  = lane >> 2;
    const int tig  = lane & 3;
    const int w16  = wid * 16;

    // staging slots: 1024 16B-copies over 256 threads = 4/thread; first 512 -> K, rest -> V
    int sK[4], sOff[4];
    uint32_t dOff[4];
    int dStr[4];
    #pragma unroll
    for (int it = 0; it < 4; it++) {
        int s   = tid + it * 256;
        int r   = (s & 511) >> 3;
        int d4  = (s & 7) * 4;
        sK[it]  = r;
        if (s < 512) {
            sOff[it] = h * 32 + d4;
            dOff[it] = smemBase + (r * KSTR + d4) * 4;
            dStr[it] = 64 * KSTR * 4;
        } else {
            sOff[it] = 256 + h * 32 + d4;
            dOff[it] = smemBase + (2 * 64 * KSTR + r * VSTR + d4) * 4;
            dStr[it] = 64 * VSTR * 4;
        }
    }

    uint32_t qf[4][4];
    {
        const size_t rlo = (size_t)(q0 + w16 + gid) * 256 + h * 32;
        const size_t rhi = (size_t)(q0 + w16 + gid + 8) * 256 + h * 32;
        #pragma unroll
        for (int ks = 0; ks < 4; ks++) {
            int k0 = ks * 8;
            qf[ks][0] = to_tf32(Q[rlo + k0 + tig]     * SCALE_L2E);
            qf[ks][1] = to_tf32(Q[rhi + k0 + tig]     * SCALE_L2E);
            qf[ks][2] = to_tf32(Q[rlo + k0 + tig + 4] * SCALE_L2E);
            qf[ks][3] = to_tf32(Q[rhi + k0 + tig + 4] * SCALE_L2E);
        }
    }

    float l_lo = 0.f, l_hi = 0.f;
    float o[4][4];
    #pragma unroll
    for (int n = 0; n < 4; n++)
        #pragma unroll
        for (int r = 0; r < 4; r++) o[n][r] = 0.f;

    const int total = N1 + N2;

    // prologue: async-copy chunk 0 into buffer 0
    #pragma unroll
    for (int it = 0; it < 4; it++) {
        int kg = sK[it];
        const float* base = (kg < N1) ? (KV1 + (size_t)kg * 512)
                                      : (KV2 + (size_t)(kg - N1) * 512);
        cp_async16(dOff[it], base + sOff[it]);
    }
    asm volatile("cp.async.commit_group;" ::: "memory");

    int c = 0;
    for (int c0 = 0; c0 < total; c0 += 64, c++) {
        const int cur = c & 1;
        asm volatile("cp.async.wait_group 0;" ::: "memory");
        __syncthreads();

        // kick off next chunk's copy (overlaps compute)
        if (c0 + 64 < total) {
            int cn = c0 + 64;
            const int nxt = cur ^ 1;
            #pragma unroll
            for (int it = 0; it < 4; it++) {
                int kg = cn + sK[it];
                const float* base = (kg < N1) ? (KV1 + (size_t)kg * 512)
                                              : (KV2 + (size_t)(kg - N1) * 512);
                cp_async16(dOff[it] + nxt * dStr[it], base + sOff[it]);
            }
            asm volatile("cp.async.commit_group;" ::: "memory");
        }

        const uint32_t* Kc = KsB + cur * 64 * KSTR;
        const uint32_t* Vc = VsB + cur * 64 * VSTR;

        // S = Q @ K^T (log2 domain)
        float s[8][4];
        #pragma unroll
        for (int n = 0; n < 8; n++) {
            s[n][0] = s[n][1] = s[n][2] = s[n][3] = 0.f;
            #pragma unroll
            for (int ks = 0; ks < 4; ks++) {
                uint32_t b[2];
                b[0] = Kc[(n * 8 + gid) * KSTR + ks * 8 + tig];
                b[1] = Kc[(n * 8 + gid) * KSTR + ks * 8 + tig + 4];
                mma_tf32(s[n], qf[ks], b, s[n]);
            }
        }

        // softmax numerator via ex2
        float rs_lo = 0.f, rs_hi = 0.f;
        #pragma unroll
        for (int n = 0; n < 8; n++) {
            s[n][0] = ex2(s[n][0]);
            s[n][1] = ex2(s[n][1]);
            s[n][2] = ex2(s[n][2]);
            s[n][3] = ex2(s[n][3]);
            rs_lo += s[n][0] + s[n][1];
            rs_hi += s[n][2] + s[n][3];
        }
        rs_lo += __shfl_xor_sync(FULL, rs_lo, 1);
        rs_lo += __shfl_xor_sync(FULL, rs_lo, 2);
        rs_hi += __shfl_xor_sync(FULL, rs_hi, 1);
        rs_hi += __shfl_xor_sync(FULL, rs_hi, 2);
        l_lo += rs_lo;
        l_hi += rs_hi;

        // stage P (tf32-rounded)
        #pragma unroll
        for (int n = 0; n < 8; n++) {
            int col = n * 8 + 2 * tig;
            Ps[(w16 + gid) * PSTR + col]         = to_tf32(s[n][0]);
            Ps[(w16 + gid) * PSTR + col + 1]     = to_tf32(s[n][1]);
            Ps[(w16 + gid + 8) * PSTR + col]     = to_tf32(s[n][2]);
            Ps[(w16 + gid + 8) * PSTR + col + 1] = to_tf32(s[n][3]);
        }
        __syncwarp();

        // O += P @ V
        #pragma unroll
        for (int ks = 0; ks < 8; ks++) {
            uint32_t af[4];
            af[0] = Ps[(w16 + gid) * PSTR + ks * 8 + tig];
            af[1] = Ps[(w16 + gid + 8) * PSTR + ks * 8 + tig];
            af[2] = Ps[(w16 + gid) * PSTR + ks * 8 + tig + 4];
            af[3] = Ps[(w16 + gid + 8) * PSTR + ks * 8 + tig + 4];
            #pragma unroll
            for (int nd = 0; nd < 4; nd++) {
                uint32_t b[2];
                b[0] = Vc[(ks * 8 + tig) * VSTR + nd * 8 + gid];
                b[1] = Vc[(ks * 8 + tig + 4) * VSTR + nd * 8 + gid];
                mma_tf32(o[nd], af, b, o[nd]);
            }
        }
    }

    float inv_lo = 1.f / l_lo;
    float inv_hi = 1.f / l_hi;
    const size_t rlo = (size_t)(q0 + w16 + gid) * 256 + h * 32;
    const size_t rhi = (size_t)(q0 + w16 + gid + 8) * 256 + h * 32;
    #pragma unroll
    for (int nd = 0; nd < 4; nd++) {
        int col = nd * 8 + 2 * tig;
        O[rlo + col]     = o[nd][0] * inv_lo;
        O[rlo + col + 1] = o[nd][1] * inv_lo;
        O[rhi + col]     = o[nd][2] * inv_hi;
        O[rhi + col + 1] = o[nd][3] * inv_hi;
    }
}

// ---------------- launch ----------------
extern "C" void kernel_launch(void* const* d_in, const int* in_sizes, int n_in,
                              void* d_out, int out_size)
{
    const float* x   = (const float*)d_in[0];
    const float* y   = (const float*)d_in[1];
    const float* Wq  = (const float*)d_in[2];
    const float* Wkv = (const float*)d_in[3];
    const float* srw = (const float*)d_in[4];
    const float* srb = (const float*)d_in[5];
    const float* lng = (const float*)d_in[6];
    const float* lnb = (const float*)d_in[7];
    const float* pw  = (const float*)d_in[8];
    const float* pb  = (const float*)d_in[9];
    float* out = (float*)d_out;

    float *q, *o, *red, *kv, *kvym, *srwT;
    cudaGetSymbolAddress((void**)&q,    g_q);
    cudaGetSymbolAddress((void**)&o,    g_o);
    cudaGetSymbolAddress((void**)&red,  g_red);
    cudaGetSymbolAddress((void**)&kv,   g_kv);
    cudaGetSymbolAddress((void**)&kvym, g_kvym);
    cudaGetSymbolAddress((void**)&srwT, g_srwT);

    float* kvy = kv + (size_t)NRX * 512;

    constexpr int SMEM128 = (2 * 128 * ASTR + 2 * 32 * BSTR) * 4;   // 55296 B
    cudaFuncSetAttribute(mma_gemm128_kernel,
                         cudaFuncAttributeMaxDynamicSharedMemorySize, SMEM128);
    cudaFuncSetAttribute(attn_mma_kernel,
                         cudaFuncAttributeMaxDynamicSharedMemorySize, ATTN_SMEM);

    transpose_w_kernel<<<1024, 256>>>(srw, srwT);

    // Q projection (merged, 128-row tiles)
    mma_gemm128_kernel<<<dim3(DIM / 64, MQ / 128), 256, SMEM128>>>(
        x, y, NX, Wq, nullptr, q, MQ, DIM, DIM);

    // SR conv (merged) + LN
    mma_conv_kernel<<<dim3(DIM / 64, MR / 64), 256>>>(x, y, srwT, srb, red);
    ln_kernel<<<MR, 256>>>(red, lng, lnb);

    // KV projection (merged, output pre-rounded to tf32)
    mma_gemm_kernel<<<dim3(2 * DIM / 64, MR / 64), 256>>>(red, red, MR, Wkv, nullptr, kv, MR, 2 * DIM, DIM, 1);

    // batch-mean support KV (tf32-rounded)
    meankv_kernel<<<(NRY * 2 * DIM) / 256, 256>>>(kvy, kvym);

    // attention (merged; 128-query tiles; grid 82 x 8)
    attn_mma_kernel<<<dim3(XBLK2 + BY * YBLK2, HEADS), 256, ATTN_SMEM>>>(
        q, kv, kvy, kvym, o, NRX, NRY);

    // output projection (merged, 128-row tiles) into d_out
    mma_gemm128_kernel<<<dim3(DIM / 64, MQ / 128), 256, SMEM128>>>(
        o, o, MQ, pw, pb, out, MQ, DIM, DIM);
}

// round 16
// speedup vs baseline: 1.0018x; 1.0018x over previous
#include <cuda_runtime.h>
#include <math.h>
#include <stdint.h>

#define FULL 0xffffffffu

// ---------------- problem constants ----------------
constexpr int DIM   = 256;
constexpr int HEADS = 8;
constexpr float SCALE_L2E = 0.17677669529663687f * 1.4426950408889634f;

constexpr int NX  = 6400;
constexpr int NY  = 1024;
constexpr int BY  = 4;
constexpr int NRX = 1600;
constexpr int NRY = 256;
constexpr int MQ  = NX + BY * NY;      // 10496
constexpr int MR  = NRX + BY * NRY;    // 2624
constexpr int XBLK = NX / 64;          // 100
constexpr int YBLK = NY / 64;          // 16

// ---------------- scratch (device globals) ----------------
__device__ float g_q   [MQ * DIM];
__device__ float g_o   [MQ * DIM];
__device__ float g_red [MR * DIM];
__device__ float g_kv  [MR * 2 * DIM];
__device__ float g_kvym[NRY * 2 * DIM];
__device__ float g_srwT[1024 * DIM];

// ---------------- tf32 helpers ----------------
__device__ __forceinline__ uint32_t to_tf32(float f) {
    uint32_t r; asm("cvt.rna.tf32.f32 %0, %1;" : "=r"(r) : "f"(f)); return r;
}
__device__ __forceinline__ uint4 cvt4(uint4 v) {
    uint4 r;
    r.x = to_tf32(__uint_as_float(v.x));
    r.y = to_tf32(__uint_as_float(v.y));
    r.z = to_tf32(__uint_as_float(v.z));
    r.w = to_tf32(__uint_as_float(v.w));
    return r;
}
__device__ __forceinline__ void mma_tf32(float* d, const uint32_t* a, const uint32_t* b,
                                         const float* c)
{
    asm volatile(
        "mma.sync.aligned.m16n8k8.row.col.f32.tf32.tf32.f32 "
        "{%0,%1,%2,%3}, {%4,%5,%6,%7}, {%8,%9}, {%10,%11,%12,%13};"
        : "=f"(d[0]), "=f"(d[1]), "=f"(d[2]), "=f"(d[3])
        : "r"(a[0]), "r"(a[1]), "r"(a[2]), "r"(a[3]),
          "r"(b[0]), "r"(b[1]),
          "f"(c[0]), "f"(c[1]), "f"(c[2]), "f"(c[3]));
}
__device__ __forceinline__ float ex2(float x) {
    float r; asm("ex2.approx.f32 %0, %1;" : "=f"(r) : "f"(x)); return r;
}
__device__ __forceinline__ void cp_async16(uint32_t dst, const void* src) {
    asm volatile("cp.async.cg.shared.global [%0], [%1], 16;" :: "r"(dst), "l"(src));
}

// ---------------- weight transpose ----------------
__global__ void transpose_w_kernel(const float* __restrict__ srw, float* __restrict__ wT)
{
    int idx = blockIdx.x * 256 + threadIdx.x;
    int o = idx >> 10;
    int k = idx & 1023;
    wT[k * 256 + o] = srw[idx];
}

constexpr int ASTR = 36;
constexpr int BSTR = 72;

// ============ tf32 MMA GEMM, 64x64 tile (KV proj; optional tf32-rounded output) ============
__global__ void __launch_bounds__(256) mma_gemm_kernel(
    const float* __restrict__ A1, const float* __restrict__ A2, int rowSplit,
    const float* __restrict__ B, const float* __restrict__ bias,
    float* __restrict__ C, int M, int N, int K, int roundC)
{
    __shared__ uint32_t As[2][64][ASTR];
    __shared__ uint32_t Bs[2][32][BSTR];

    const int tid  = threadIdx.x;
    const int wid  = tid >> 5;
    const int lane = tid & 31;
    const int gid  = lane >> 2;
    const int tig  = lane & 3;
    const int w16  = (wid >> 1) * 16;
    const int c32  = (wid & 1) * 32;
    const int rowBase = blockIdx.y * 64;
    const int colBase = blockIdx.x * 64;

    const float* aPtr[2];
    int aR[2], aC[2];
    #pragma unroll
    for (int it = 0; it < 2; it++) {
        int e  = tid + it * 256;
        aR[it] = e >> 3;
        aC[it] = (e & 7) * 4;
        int m  = rowBase + aR[it];
        aPtr[it] = (m < rowSplit) ? (A1 + (size_t)m * K)
                                  : (A2 + (size_t)(m - rowSplit) * K);
    }
    const float* bPtr[2];
    int bR[2], bC[2];
    #pragma unroll
    for (int it = 0; it < 2; it++) {
        int e  = tid + it * 256;
        bR[it] = e >> 4;
        bC[it] = (e & 15) * 4;
        bPtr[it] = B + (size_t)bR[it] * N + colBase + bC[it];
    }

    float acc[4][4];
    #pragma unroll
    for (int n = 0; n < 4; n++)
        #pragma unroll
        for (int r = 0; r < 4; r++) acc[n][r] = 0.f;

    const int nChunks = K >> 5;
    uint4 aReg[2], bReg[2];

    #pragma unroll
    for (int it = 0; it < 2; it++) {
        aReg[it] = *(const uint4*)&aPtr[it][aC[it]];
        bReg[it] = *(const uint4*)&bPtr[it][0];
    }
    #pragma unroll
    for (int it = 0; it < 2; it++) {
        *(uint4*)&As[0][aR[it]][aC[it]] = cvt4(aReg[it]);
        *(uint4*)&Bs[0][bR[it]][bC[it]] = cvt4(bReg[it]);
    }

    for (int c = 0; c < nChunks; c++) {
        const int cur = c & 1;
        __syncthreads();
        if (c + 1 < nChunks) {
            int k0 = (c + 1) << 5;
            #pragma unroll
            for (int it = 0; it < 2; it++) {
                aReg[it] = *(const uint4*)&aPtr[it][k0 + aC[it]];
                bReg[it] = *(const uint4*)&bPtr[it][(size_t)k0 * N];
            }
        }

        #pragma unroll
        for (int ks = 0; ks < 4; ks++) {
            uint32_t af[4];
            af[0] = As[cur][w16 + gid][ks * 8 + tig];
            af[1] = As[cur][w16 + gid + 8][ks * 8 + tig];
            af[2] = As[cur][w16 + gid][ks * 8 + tig + 4];
            af[3] = As[cur][w16 + gid + 8][ks * 8 + tig + 4];
            #pragma unroll
            for (int n = 0; n < 4; n++) {
                uint32_t bf[2];
                bf[0] = Bs[cur][ks * 8 + tig][c32 + n * 8 + gid];
                bf[1] = Bs[cur][ks * 8 + tig + 4][c32 + n * 8 + gid];
                mma_tf32(acc[n], af, bf, acc[n]);
            }
        }

        if (c + 1 < nChunks) {
            const int nxt = cur ^ 1;
            #pragma unroll
            for (int it = 0; it < 2; it++) {
                *(uint4*)&As[nxt][aR[it]][aC[it]] = cvt4(aReg[it]);
                *(uint4*)&Bs[nxt][bR[it]][bC[it]] = cvt4(bReg[it]);
            }
        }
    }

    const size_t rlo = (size_t)(rowBase + w16 + gid) * N;
    const size_t rhi = (size_t)(rowBase + w16 + gid + 8) * N;
    #pragma unroll
    for (int n = 0; n < 4; n++) {
        int col = colBase + c32 + n * 8 + 2 * tig;
        float b0 = bias ? bias[col]     : 0.f;
        float b1 = bias ? bias[col + 1] : 0.f;
        float v00 = acc[n][0] + b0, v01 = acc[n][1] + b1;
        float v10 = acc[n][2] + b0, v11 = acc[n][3] + b1;
        if (roundC) {
            v00 = __uint_as_float(to_tf32(v00));
            v01 = __uint_as_float(to_tf32(v01));
            v10 = __uint_as_float(to_tf32(v10));
            v11 = __uint_as_float(to_tf32(v11));
        }
        *(float2*)&C[rlo + col] = make_float2(v00, v01);
        *(float2*)&C[rhi + col] = make_float2(v10, v11);
    }
}

// ============ tf32 MMA GEMM, 128x64 tile, dynamic smem (Q proj / out proj) ============
__global__ void __launch_bounds__(256) mma_gemm128_kernel(
    const float* __restrict__ A1, const float* __restrict__ A2, int rowSplit,
    const float* __restrict__ B, const float* __restrict__ bias,
    float* __restrict__ C, int M, int N, int K)
{
    extern __shared__ uint32_t smemBuf[];
    auto As = (uint32_t(*)[128][ASTR]) smemBuf;
    auto Bs = (uint32_t(*)[32][BSTR]) (smemBuf + 2 * 128 * ASTR);

    const int tid  = threadIdx.x;
    const int wid  = tid >> 5;
    const int lane = tid & 31;
    const int gid  = lane >> 2;
    const int tig  = lane & 3;
    const int r32  = (wid >> 1) * 32;
    const int c32  = (wid & 1) * 32;
    const int rowBase = blockIdx.y * 128;
    const int colBase = blockIdx.x * 64;

    const float* aPtr[4];
    int aR[4], aC[4];
    #pragma unroll
    for (int it = 0; it < 4; it++) {
        int e  = tid + it * 256;
        aR[it] = e >> 3;
        aC[it] = (e & 7) * 4;
        int m  = rowBase + aR[it];
        aPtr[it] = (m < rowSplit) ? (A1 + (size_t)m * K)
                                  : (A2 + (size_t)(m - rowSplit) * K);
    }
    const float* bPtr[2];
    int bR[2], bC[2];
    #pragma unroll
    for (int it = 0; it < 2; it++) {
        int e  = tid + it * 256;
        bR[it] = e >> 4;
        bC[it] = (e & 15) * 4;
        bPtr[it] = B + (size_t)bR[it] * N + colBase + bC[it];
    }

    float acc[2][4][4];
    #pragma unroll
    for (int m = 0; m < 2; m++)
        #pragma unroll
        for (int n = 0; n < 4; n++)
            #pragma unroll
            for (int r = 0; r < 4; r++) acc[m][n][r] = 0.f;

    const int nChunks = K >> 5;
    uint4 aReg[4], bReg[2];

    #pragma unroll
    for (int it = 0; it < 4; it++) aReg[it] = *(const uint4*)&aPtr[it][aC[it]];
    #pragma unroll
    for (int it = 0; it < 2; it++) bReg[it] = *(const uint4*)&bPtr[it][0];
    #pragma unroll
    for (int it = 0; it < 4; it++) *(uint4*)&As[0][aR[it]][aC[it]] = cvt4(aReg[it]);
    #pragma unroll
    for (int it = 0; it < 2; it++) *(uint4*)&Bs[0][bR[it]][bC[it]] = cvt4(bReg[it]);

    for (int c = 0; c < nChunks; c++) {
        const int cur = c & 1;
        __syncthreads();
        if (c + 1 < nChunks) {
            int k0 = (c + 1) << 5;
            #pragma unroll
            for (int it = 0; it < 4; it++) aReg[it] = *(const uint4*)&aPtr[it][k0 + aC[it]];
            #pragma unroll
            for (int it = 0; it < 2; it++) bReg[it] = *(const uint4*)&bPtr[it][(size_t)k0 * N];
        }

        #pragma unroll
        for (int ks = 0; ks < 4; ks++) {
            uint32_t af[2][4];
            #pragma unroll
            for (int m = 0; m < 2; m++) {
                int rb = r32 + m * 16;
                af[m][0] = As[cur][rb + gid][ks * 8 + tig];
                af[m][1] = As[cur][rb + gid + 8][ks * 8 + tig];
                af[m][2] = As[cur][rb + gid][ks * 8 + tig + 4];
                af[m][3] = As[cur][rb + gid + 8][ks * 8 + tig + 4];
            }
            #pragma unroll
            for (int n = 0; n < 4; n++) {
                uint32_t bf[2];
                bf[0] = Bs[cur][ks * 8 + tig][c32 + n * 8 + gid];
                bf[1] = Bs[cur][ks * 8 + tig + 4][c32 + n * 8 + gid];
                mma_tf32(acc[0][n], af[0], bf, acc[0][n]);
                mma_tf32(acc[1][n], af[1], bf, acc[1][n]);
            }
        }

        if (c + 1 < nChunks) {
            const int nxt = cur ^ 1;
            #pragma unroll
            for (int it = 0; it < 4; it++) *(uint4*)&As[nxt][aR[it]][aC[it]] = cvt4(aReg[it]);
            #pragma unroll
            for (int it = 0; it < 2; it++) *(uint4*)&Bs[nxt][bR[it]][bC[it]] = cvt4(bReg[it]);
        }
    }

    #pragma unroll
    for (int m = 0; m < 2; m++) {
        const size_t rlo = (size_t)(rowBase + r32 + m * 16 + gid) * N;
        const size_t rhi = (size_t)(rowBase + r32 + m * 16 + gid + 8) * N;
        #pragma unroll
        for (int n = 0; n < 4; n++) {
            int col = colBase + c32 + n * 8 + 2 * tig;
            float b0 = bias ? bias[col]     : 0.f;
            float b1 = bias ? bias[col + 1] : 0.f;
            *(float2*)&C[rlo + col] = make_float2(acc[m][n][0] + b0, acc[m][n][1] + b1);
            *(float2*)&C[rhi + col] = make_float2(acc[m][n][2] + b0, acc[m][n][3] + b1);
        }
    }
}

// ============ merged SR conv (x + y), tf32 MMA, double-buffered ============
__global__ void __launch_bounds__(256) mma_conv_kernel(
    const float* __restrict__ X1, const float* __restrict__ X2,
    const float* __restrict__ WT, const float* __restrict__ bias,
    float* __restrict__ C)
{
    __shared__ uint32_t As[2][64][ASTR];
    __shared__ uint32_t Bs[2][32][BSTR];

    const int tid  = threadIdx.x;
    const int wid  = tid >> 5;
    const int lane = tid & 31;
    const int gid  = lane >> 2;
    const int tig  = lane & 3;
    const int w16  = (wid >> 1) * 16;
    const int c32  = (wid & 1) * 32;
    const int rowBase = blockIdx.y * 64;
    const int colBase = blockIdx.x * 64;

    const float* aPtr[2];
    int aR[2], aSc[2], aIq[2];
    #pragma unroll
    for (int it = 0; it < 2; it++) {
        int e   = tid + it * 256;
        int r   = e >> 3;
        int sub = e & 7;
        int p   = sub & 3;
        int iq  = sub >> 2;
        int kh  = p >> 1, kw = p & 1;
        int m   = rowBase + r;
        const float* src;
        int mm, srcW;
        if (m < NRX) { src = X1; mm = m; srcW = 80; }
        else {
            int t = m - NRX;
            src = X2 + (size_t)(t / NRY) * NY * 256;
            mm  = t % NRY;
            srcW = 32;
        }
        int redW = srcW >> 1;
        int oh = mm / redW, ow = mm % redW;
        int tok = (oh * 2 + kh) * srcW + (ow * 2 + kw);
        aPtr[it] = src + (size_t)tok * 256;
        aR[it]  = r;
        aSc[it] = iq * 16 + p;
        aIq[it] = iq * 4;
    }
    const float* bPtr[2];
    int bR[2], bC[2];
    #pragma unroll
    for (int it = 0; it < 2; it++) {
        int e  = tid + it * 256;
        bR[it] = e >> 4;
        bC[it] = (e & 15) * 4;
        bPtr[it] = WT + (size_t)bR[it] * 256 + colBase + bC[it];
    }

    float acc[4][4];
    #pragma unroll
    for (int n = 0; n < 4; n++)
        #pragma unroll
        for (int r = 0; r < 4; r++) acc[n][r] = 0.f;

    const int nChunks = 32;
    float4 aReg[2];
    uint4  bReg[2];

    #pragma unroll
    for (int it = 0; it < 2; it++) {
        aReg[it] = *(const float4*)&aPtr[it][aIq[it]];
        bReg[it] = *(const uint4*)&bPtr[it][0];
    }
    #pragma unroll
    for (int it = 0; it < 2; it++) {
        int sc = aSc[it];
        As[0][aR[it]][sc + 0]  = to_tf32(aReg[it].x);
        As[0][aR[it]][sc + 4]  = to_tf32(aReg[it].y);
        As[0][aR[it]][sc + 8]  = to_tf32(aReg[it].z);
        As[0][aR[it]][sc + 12] = to_tf32(aReg[it].w);
        *(uint4*)&Bs[0][bR[it]][bC[it]] = cvt4(bReg[it]);
    }

    for (int c = 0; c < nChunks; c++) {
        const int cur = c & 1;
        __syncthreads();
        if (c + 1 < nChunks) {
            int i0 = ((c + 1) << 3);
            #pragma unroll
            for (int it = 0; it < 2; it++) {
                aReg[it] = *(const float4*)&aPtr[it][i0 + aIq[it]];
                bReg[it] = *(const uint4*)&bPtr[it][(size_t)((c + 1) << 5) * 256];
            }
        }

        #pragma unroll
        for (int ks = 0; ks < 4; ks++) {
            uint32_t af[4];
            af[0] = As[cur][w16 + gid][ks * 8 + tig];
            af[1] = As[cur][w16 + gid + 8][ks * 8 + tig];
            af[2] = As[cur][w16 + gid][ks * 8 + tig + 4];
            af[3] = As[cur][w16 + gid + 8][ks * 8 + tig + 4];
            #pragma unroll
            for (int n = 0; n < 4; n++) {
                uint32_t bf[2];
                bf[0] = Bs[cur][ks * 8 + tig][c32 + n * 8 + gid];
                bf[1] = Bs[cur][ks * 8 + tig + 4][c32 + n * 8 + gid];
                mma_tf32(acc[n], af, bf, acc[n]);
            }
        }

        if (c + 1 < nChunks) {
            const int nxt = cur ^ 1;
            #pragma unroll
            for (int it = 0; it < 2; it++) {
                int sc = aSc[it];
                As[nxt][aR[it]][sc + 0]  = to_tf32(aReg[it].x);
                As[nxt][aR[it]][sc + 4]  = to_tf32(aReg[it].y);
                As[nxt][aR[it]][sc + 8]  = to_tf32(aReg[it].z);
                As[nxt][aR[it]][sc + 12] = to_tf32(aReg[it].w);
                *(uint4*)&Bs[nxt][bR[it]][bC[it]] = cvt4(bReg[it]);
            }
        }
    }

    const size_t rlo = (size_t)(rowBase + w16 + gid) * 256;
    const size_t rhi = (size_t)(rowBase + w16 + gid + 8) * 256;
    #pragma unroll
    for (int n = 0; n < 4; n++) {
        int col = colBase + c32 + n * 8 + 2 * tig;
        float b0 = bias[col];
        float b1 = bias[col + 1];
        *(float2*)&C[rlo + col] = make_float2(acc[n][0] + b0, acc[n][1] + b1);
        *(float2*)&C[rhi + col] = make_float2(acc[n][2] + b0, acc[n][3] + b1);
    }
}

// ---------------- LayerNorm (in place) ----------------
__global__ void ln_kernel(float* __restrict__ red, const float* __restrict__ g,
                          const float* __restrict__ b)
{
    const int t = blockIdx.x;
    const int c = threadIdx.x;
    __shared__ float sh[8];
    __shared__ float s_mean, s_rstd;

    float v = red[(size_t)t * 256 + c];

    float x = v;
    #pragma unroll
    for (int o = 16; o > 0; o >>= 1) x += __shfl_xor_sync(FULL, x, o);
    if ((c & 31) == 0) sh[c >> 5] = x;
    __syncthreads();
    if (c == 0) {
        float s = 0.f;
        #pragma unroll
        for (int i = 0; i < 8; i++) s += sh[i];
        s_mean = s * (1.0f / 256.0f);
    }
    __syncthreads();

    float d = v - s_mean;
    float x2 = d * d;
    #pragma unroll
    for (int o = 16; o > 0; o >>= 1) x2 += __shfl_xor_sync(FULL, x2, o);
    if ((c & 31) == 0) sh[c >> 5] = x2;
    __syncthreads();
    if (c == 0) {
        float s = 0.f;
        #pragma unroll
        for (int i = 0; i < 8; i++) s += sh[i];
        s_rstd = rsqrtf(s * (1.0f / 256.0f) + 1e-5f);
    }
    __syncthreads();

    red[(size_t)t * 256 + c] = d * s_rstd * g[c] + b[c];
}

// ---------------- batch mean of support KV (tf32-rounded output) ----------------
__global__ void meankv_kernel(const float* __restrict__ kvy, float* __restrict__ out)
{
    int idx = blockIdx.x * 256 + threadIdx.x;
    const int STRIDE = NRY * 2 * DIM;
    float v = 0.25f * (kvy[idx] + kvy[idx + STRIDE] + kvy[idx + 2 * STRIDE] + kvy[idx + 3 * STRIDE]);
    out[idx] = __uint_as_float(to_tf32(v));
}

// ---------------- tf32 MMA flash attention (R14: 64-q tiles, cp.async pipeline) ----------------
constexpr int KSTR = 36;
constexpr int VSTR = 40;
constexpr int PSTR = 68;
constexpr int ATTN_SMEM = (2 * 64 * KSTR + 2 * 64 * VSTR + 64 * PSTR) * 4;  // 56320 B

__global__ void __launch_bounds__(128) attn_mma_kernel(
    const float* __restrict__ q_all, const float* __restrict__ KV1,
    const float* __restrict__ kvy, const float* __restrict__ kvym,
    float* __restrict__ o_all, int N1, int N2)
{
    extern __shared__ uint32_t dyn[];
    uint32_t* KsB = dyn;
    uint32_t* VsB = dyn + 2 * 64 * KSTR;
    uint32_t* Ps  = dyn + 2 * 64 * KSTR + 2 * 64 * VSTR;
    const uint32_t smemBase = (uint32_t)__cvta_generic_to_shared(dyn);

    const int h  = blockIdx.y;
    const int bx = blockIdx.x;

    const float* Q;
    float*       O;
    const float* KV2;
    int q0;
    if (bx < XBLK) {
        Q = q_all; O = o_all; KV2 = kvym; q0 = bx * 64;
    } else {
        int t  = bx - XBLK;
        int bz = t >> 4;
        int qb = t & 15;
        size_t off = (size_t)(NX + bz * NY) * 256;
        Q = q_all + off; O = o_all + off;
        KV2 = kvy + (size_t)bz * NRY * 512;
        q0 = qb * 64;
    }

    const int tid  = threadIdx.x;
    const int wid  = tid >> 5;
    const int lane = tid & 31;
    const int gid  = lane >> 2;
    const int tig  = lane & 3;
    const int w16  = wid * 16;

    int sK[8], sOff[8];
    uint32_t dOff[8];
    int dStr[8];
    #pragma unroll
    for (int it = 0; it < 8; it++) {
        int s   = tid + it * 128;
        int r   = (s & 511) >> 3;
        int d4  = (s & 7) * 4;
        sK[it]  = r;
        if (s < 512) {
            sOff[it] = h * 32 + d4;
            dOff[it] = smemBase + (r * KSTR + d4) * 4;
            dStr[it] = 64 * KSTR * 4;
        } else {
            sOff[it] = 256 + h * 32 + d4;
            dOff[it] = smemBase + (2 * 64 * KSTR + r * VSTR + d4) * 4;
            dStr[it] = 64 * VSTR * 4;
        }
    }

    uint32_t qf[4][4];
    {
        const size_t rlo = (size_t)(q0 + w16 + gid) * 256 + h * 32;
        const size_t rhi = (size_t)(q0 + w16 + gid + 8) * 256 + h * 32;
        #pragma unroll
        for (int ks = 0; ks < 4; ks++) {
            int k0 = ks * 8;
            qf[ks][0] = to_tf32(Q[rlo + k0 + tig]     * SCALE_L2E);
            qf[ks][1] = to_tf32(Q[rhi + k0 + tig]     * SCALE_L2E);
            qf[ks][2] = to_tf32(Q[rlo + k0 + tig + 4] * SCALE_L2E);
            qf[ks][3] = to_tf32(Q[rhi + k0 + tig + 4] * SCALE_L2E);
        }
    }

    float l_lo = 0.f, l_hi = 0.f;
    float o[4][4];
    #pragma unroll
    for (int n = 0; n < 4; n++)
        #pragma unroll
        for (int r = 0; r < 4; r++) o[n][r] = 0.f;

    const int total = N1 + N2;

    #pragma unroll
    for (int it = 0; it < 8; it++) {
        int kg = sK[it];
        const float* base = (kg < N1) ? (KV1 + (size_t)kg * 512)
                                      : (KV2 + (size_t)(kg - N1) * 512);
        cp_async16(dOff[it], base + sOff[it]);
    }
    asm volatile("cp.async.commit_group;" ::: "memory");

    int c = 0;
    for (int c0 = 0; c0 < total; c0 += 64, c++) {
        const int cur = c & 1;
        asm volatile("cp.async.wait_group 0;" ::: "memory");
        __syncthreads();

        if (c0 + 64 < total) {
            int cn = c0 + 64;
            const int nxt = cur ^ 1;
            #pragma unroll
            for (int it = 0; it < 8; it++) {
                int kg = cn + sK[it];
                const float* base = (kg < N1) ? (KV1 + (size_t)kg * 512)
                                              : (KV2 + (size_t)(kg - N1) * 512);
                cp_async16(dOff[it] + nxt * dStr[it], base + sOff[it]);
            }
            asm volatile("cp.async.commit_group;" ::: "memory");
        }

        const uint32_t* Kc = KsB + cur * 64 * KSTR;
        const uint32_t* Vc = VsB + cur * 64 * VSTR;

        float s[8][4];
        #pragma unroll
        for (int n = 0; n < 8; n++) {
            s[n][0] = s[n][1] = s[n][2] = s[n][3] = 0.f;
            #pragma unroll
            for (int ks = 0; ks < 4; ks++) {
                uint32_t b[2];
                b[0] = Kc[(n * 8 + gid) * KSTR + ks * 8 + tig];
                b[1] = Kc[(n * 8 + gid) * KSTR + ks * 8 + tig + 4];
                mma_tf32(s[n], qf[ks], b, s[n]);
            }
        }

        float rs_lo = 0.f, rs_hi = 0.f;
        #pragma unroll
        for (int n = 0; n < 8; n++) {
            s[n][0] = ex2(s[n][0]);
            s[n][1] = ex2(s[n][1]);
            s[n][2] = ex2(s[n][2]);
            s[n][3] = ex2(s[n][3]);
            rs_lo += s[n][0] + s[n][1];
            rs_hi += s[n][2] + s[n][3];
        }
        rs_lo += __shfl_xor_sync(FULL, rs_lo, 1);
        rs_lo += __shfl_xor_sync(FULL, rs_lo, 2);
        rs_hi += __shfl_xor_sync(FULL, rs_hi, 1);
        rs_hi += __shfl_xor_sync(FULL, rs_hi, 2);
        l_lo += rs_lo;
        l_hi += rs_hi;

        #pragma unroll
        for (int n = 0; n < 8; n++) {
            int col = n * 8 + 2 * tig;
            Ps[(w16 + gid) * PSTR + col]         = to_tf32(s[n][0]);
            Ps[(w16 + gid) * PSTR + col + 1]     = to_tf32(s[n][1]);
            Ps[(w16 + gid + 8) * PSTR + col]     = to_tf32(s[n][2]);
            Ps[(w16 + gid + 8) * PSTR + col + 1] = to_tf32(s[n][3]);
        }
        __syncwarp();

        #pragma unroll
        for (int ks = 0; ks < 8; ks++) {
            uint32_t af[4];
            af[0] = Ps[(w16 + gid) * PSTR + ks * 8 + tig];
            af[1] = Ps[(w16 + gid + 8) * PSTR + ks * 8 + tig];
            af[2] = Ps[(w16 + gid) * PSTR + ks * 8 + tig + 4];
            af[3] = Ps[(w16 + gid + 8) * PSTR + ks * 8 + tig + 4];
            #pragma unroll
            for (int nd = 0; nd < 4; nd++) {
                uint32_t b[2];
                b[0] = Vc[(ks * 8 + tig) * VSTR + nd * 8 + gid];
                b[1] = Vc[(ks * 8 + tig + 4) * VSTR + nd * 8 + gid];
                mma_tf32(o[nd], af, b, o[nd]);
            }
        }
    }

    float inv_lo = 1.f / l_lo;
    float inv_hi = 1.f / l_hi;
    const size_t rlo = (size_t)(q0 + w16 + gid) * 256 + h * 32;
    const size_t rhi = (size_t)(q0 + w16 + gid + 8) * 256 + h * 32;
    #pragma unroll
    for (int nd = 0; nd < 4; nd++) {
        int col = nd * 8 + 2 * tig;
        O[rlo + col]     = o[nd][0] * inv_lo;
        O[rlo + col + 1] = o[nd][1] * inv_lo;
        O[rhi + col]     = o[nd][2] * inv_hi;
        O[rhi + col + 1] = o[nd][3] * inv_hi;
    }
}

// ---------------- launch ----------------
extern "C" void kernel_launch(void* const* d_in, const int* in_sizes, int n_in,
                              void* d_out, int out_size)
{
    const float* x   = (const float*)d_in[0];
    const float* y   = (const float*)d_in[1];
    const float* Wq  = (const float*)d_in[2];
    const float* Wkv = (const float*)d_in[3];
    const float* srw = (const float*)d_in[4];
    const float* srb = (const float*)d_in[5];
    const float* lng = (const float*)d_in[6];
    const float* lnb = (const float*)d_in[7];
    const float* pw  = (const float*)d_in[8];
    const float* pb  = (const float*)d_in[9];
    float* out = (float*)d_out;

    float *q, *o, *red, *kv, *kvym, *srwT;
    cudaGetSymbolAddress((void**)&q,    g_q);
    cudaGetSymbolAddress((void**)&o,    g_o);
    cudaGetSymbolAddress((void**)&red,  g_red);
    cudaGetSymbolAddress((void**)&kv,   g_kv);
    cudaGetSymbolAddress((void**)&kvym, g_kvym);
    cudaGetSymbolAddress((void**)&srwT, g_srwT);

    float* kvy = kv + (size_t)NRX * 512;

    constexpr int SMEM128 = (2 * 128 * ASTR + 2 * 32 * BSTR) * 4;   // 55296 B
    static cudaStream_t s2;
    static cudaEvent_t evFork, evJoin;
    static bool inited = false;
    if (!inited) {
        cudaFuncSetAttribute(mma_gemm128_kernel,
                             cudaFuncAttributeMaxDynamicSharedMemorySize, SMEM128);
        cudaFuncSetAttribute(attn_mma_kernel,
                             cudaFuncAttributeMaxDynamicSharedMemorySize, ATTN_SMEM);
        cudaStreamCreateWithFlags(&s2, cudaStreamNonBlocking);
        cudaEventCreateWithFlags(&evFork, cudaEventDisableTiming);
        cudaEventCreateWithFlags(&evJoin, cudaEventDisableTiming);
        inited = true;
    }

    // ---- fork: Q projection runs on s2 concurrently with the KV chain ----
    cudaEventRecord(evFork, 0);
    cudaStreamWaitEvent(s2, evFork, 0);

    mma_gemm128_kernel<<<dim3(DIM / 64, MQ / 128), 256, SMEM128, s2>>>(
        x, y, NX, Wq, nullptr, q, MQ, DIM, DIM);

    // main stream: SR conv chain
    transpose_w_kernel<<<1024, 256>>>(srw, srwT);
    mma_conv_kernel<<<dim3(DIM / 64, MR / 64), 256>>>(x, y, srwT, srb, red);
    ln_kernel<<<MR, 256>>>(red, lng, lnb);
    mma_gemm_kernel<<<dim3(2 * DIM / 64, MR / 64), 256>>>(red, red, MR, Wkv, nullptr, kv, MR, 2 * DIM, DIM, 1);
    meankv_kernel<<<(NRY * 2 * DIM) / 256, 256>>>(kvy, kvym);

    // ---- join: attention needs Q (s2) and KV (main) ----
    cudaEventRecord(evJoin, s2);
    cudaStreamWaitEvent(0, evJoin, 0);

    attn_mma_kernel<<<dim3(XBLK + BY * YBLK, HEADS), 128, ATTN_SMEM>>>(
        q, kv, kvy, kvym, o, NRX, NRY);

    mma_gemm128_kernel<<<dim3(DIM / 64, MQ / 128), 256, SMEM128>>>(
        o, o, MQ, pw, pb, out, MQ, DIM, DIM);
}

// round 17
// speedup vs baseline: 1.0097x; 1.0078x over previous
#include <cuda_runtime.h>
#include <math.h>
#include <stdint.h>

#define FULL 0xffffffffu

// ---------------- problem constants ----------------
constexpr int DIM   = 256;
constexpr int HEADS = 8;
constexpr float SCALE_L2E = 0.17677669529663687f * 1.4426950408889634f;

constexpr int NX  = 6400;
constexpr int NY  = 1024;
constexpr int BY  = 4;
constexpr int NRX = 1600;
constexpr int NRY = 256;
constexpr int MQ  = NX + BY * NY;      // 10496
constexpr int MR  = NRX + BY * NRY;    // 2624
constexpr int XBLK = NX / 64;          // 100
constexpr int YBLK = NY / 64;          // 16
constexpr int NKEY = NRX + NRY;        // 1856 keys for every query
constexpr int KMID = 896;              // key-split boundary (14 / 15 chunks)

// ---------------- scratch (device globals) ----------------
__device__ float g_q   [MQ * DIM];
__device__ float g_o   [MQ * DIM];
__device__ float g_red [MR * DIM];
__device__ float g_kv  [MR * 2 * DIM];
__device__ float g_kvym[NRY * 2 * DIM];
__device__ float g_srwT[1024 * DIM];
__device__ float g_po  [2 * MQ * DIM];     // unnormalized attention partials
__device__ float g_pl  [2 * MQ * HEADS];   // softmax denominators

// ---------------- tf32 helpers ----------------
__device__ __forceinline__ uint32_t to_tf32(float f) {
    uint32_t r; asm("cvt.rna.tf32.f32 %0, %1;" : "=r"(r) : "f"(f)); return r;
}
__device__ __forceinline__ uint4 cvt4(uint4 v) {
    uint4 r;
    r.x = to_tf32(__uint_as_float(v.x));
    r.y = to_tf32(__uint_as_float(v.y));
    r.z = to_tf32(__uint_as_float(v.z));
    r.w = to_tf32(__uint_as_float(v.w));
    return r;
}
__device__ __forceinline__ void mma_tf32(float* d, const uint32_t* a, const uint32_t* b,
                                         const float* c)
{
    asm volatile(
        "mma.sync.aligned.m16n8k8.row.col.f32.tf32.tf32.f32 "
        "{%0,%1,%2,%3}, {%4,%5,%6,%7}, {%8,%9}, {%10,%11,%12,%13};"
        : "=f"(d[0]), "=f"(d[1]), "=f"(d[2]), "=f"(d[3])
        : "r"(a[0]), "r"(a[1]), "r"(a[2]), "r"(a[3]),
          "r"(b[0]), "r"(b[1]),
          "f"(c[0]), "f"(c[1]), "f"(c[2]), "f"(c[3]));
}
__device__ __forceinline__ float ex2(float x) {
    float r; asm("ex2.approx.f32 %0, %1;" : "=f"(r) : "f"(x)); return r;
}
__device__ __forceinline__ void cp_async16(uint32_t dst, const void* src) {
    asm volatile("cp.async.cg.shared.global [%0], [%1], 16;" :: "r"(dst), "l"(src));
}

// ---------------- weight transpose ----------------
__global__ void transpose_w_kernel(const float* __restrict__ srw, float* __restrict__ wT)
{
    int idx = blockIdx.x * 256 + threadIdx.x;
    int o = idx >> 10;
    int k = idx & 1023;
    wT[k * 256 + o] = srw[idx];
}

constexpr int ASTR = 36;
constexpr int BSTR = 72;

// ============ tf32 MMA GEMM, 64x64 tile (KV proj; optional tf32-rounded output) ============
__global__ void __launch_bounds__(256) mma_gemm_kernel(
    const float* __restrict__ A1, const float* __restrict__ A2, int rowSplit,
    const float* __restrict__ B, const float* __restrict__ bias,
    float* __restrict__ C, int M, int N, int K, int roundC)
{
    __shared__ uint32_t As[2][64][ASTR];
    __shared__ uint32_t Bs[2][32][BSTR];

    const int tid  = threadIdx.x;
    const int wid  = tid >> 5;
    const int lane = tid & 31;
    const int gid  = lane >> 2;
    const int tig  = lane & 3;
    const int w16  = (wid >> 1) * 16;
    const int c32  = (wid & 1) * 32;
    const int rowBase = blockIdx.y * 64;
    const int colBase = blockIdx.x * 64;

    const float* aPtr[2];
    int aR[2], aC[2];
    #pragma unroll
    for (int it = 0; it < 2; it++) {
        int e  = tid + it * 256;
        aR[it] = e >> 3;
        aC[it] = (e & 7) * 4;
        int m  = rowBase + aR[it];
        aPtr[it] = (m < rowSplit) ? (A1 + (size_t)m * K)
                                  : (A2 + (size_t)(m - rowSplit) * K);
    }
    const float* bPtr[2];
    int bR[2], bC[2];
    #pragma unroll
    for (int it = 0; it < 2; it++) {
        int e  = tid + it * 256;
        bR[it] = e >> 4;
        bC[it] = (e & 15) * 4;
        bPtr[it] = B + (size_t)bR[it] * N + colBase + bC[it];
    }

    float acc[4][4];
    #pragma unroll
    for (int n = 0; n < 4; n++)
        #pragma unroll
        for (int r = 0; r < 4; r++) acc[n][r] = 0.f;

    const int nChunks = K >> 5;
    uint4 aReg[2], bReg[2];

    #pragma unroll
    for (int it = 0; it < 2; it++) {
        aReg[it] = *(const uint4*)&aPtr[it][aC[it]];
        bReg[it] = *(const uint4*)&bPtr[it][0];
    }
    #pragma unroll
    for (int it = 0; it < 2; it++) {
        *(uint4*)&As[0][aR[it]][aC[it]] = cvt4(aReg[it]);
        *(uint4*)&Bs[0][bR[it]][bC[it]] = cvt4(bReg[it]);
    }

    for (int c = 0; c < nChunks; c++) {
        const int cur = c & 1;
        __syncthreads();
        if (c + 1 < nChunks) {
            int k0 = (c + 1) << 5;
            #pragma unroll
            for (int it = 0; it < 2; it++) {
                aReg[it] = *(const uint4*)&aPtr[it][k0 + aC[it]];
                bReg[it] = *(const uint4*)&bPtr[it][(size_t)k0 * N];
            }
        }

        #pragma unroll
        for (int ks = 0; ks < 4; ks++) {
            uint32_t af[4];
            af[0] = As[cur][w16 + gid][ks * 8 + tig];
            af[1] = As[cur][w16 + gid + 8][ks * 8 + tig];
            af[2] = As[cur][w16 + gid][ks * 8 + tig + 4];
            af[3] = As[cur][w16 + gid + 8][ks * 8 + tig + 4];
            #pragma unroll
            for (int n = 0; n < 4; n++) {
                uint32_t bf[2];
                bf[0] = Bs[cur][ks * 8 + tig][c32 + n * 8 + gid];
                bf[1] = Bs[cur][ks * 8 + tig + 4][c32 + n * 8 + gid];
                mma_tf32(acc[n], af, bf, acc[n]);
            }
        }

        if (c + 1 < nChunks) {
            const int nxt = cur ^ 1;
            #pragma unroll
            for (int it = 0; it < 2; it++) {
                *(uint4*)&As[nxt][aR[it]][aC[it]] = cvt4(aReg[it]);
                *(uint4*)&Bs[nxt][bR[it]][bC[it]] = cvt4(bReg[it]);
            }
        }
    }

    const size_t rlo = (size_t)(rowBase + w16 + gid) * N;
    const size_t rhi = (size_t)(rowBase + w16 + gid + 8) * N;
    #pragma unroll
    for (int n = 0; n < 4; n++) {
        int col = colBase + c32 + n * 8 + 2 * tig;
        float b0 = bias ? bias[col]     : 0.f;
        float b1 = bias ? bias[col + 1] : 0.f;
        float v00 = acc[n][0] + b0, v01 = acc[n][1] + b1;
        float v10 = acc[n][2] + b0, v11 = acc[n][3] + b1;
        if (roundC) {
            v00 = __uint_as_float(to_tf32(v00));
            v01 = __uint_as_float(to_tf32(v01));
            v10 = __uint_as_float(to_tf32(v10));
            v11 = __uint_as_float(to_tf32(v11));
        }
        *(float2*)&C[rlo + col] = make_float2(v00, v01);
        *(float2*)&C[rhi + col] = make_float2(v10, v11);
    }
}

// ============ tf32 MMA GEMM, 128x64 tile, dynamic smem (Q proj / out proj) ============
__global__ void __launch_bounds__(256) mma_gemm128_kernel(
    const float* __restrict__ A1, const float* __restrict__ A2, int rowSplit,
    const float* __restrict__ B, const float* __restrict__ bias,
    float* __restrict__ C, int M, int N, int K)
{
    extern __shared__ uint32_t smemBuf[];
    auto As = (uint32_t(*)[128][ASTR]) smemBuf;
    auto Bs = (uint32_t(*)[32][BSTR]) (smemBuf + 2 * 128 * ASTR);

    const int tid  = threadIdx.x;
    const int wid  = tid >> 5;
    const int lane = tid & 31;
    const int gid  = lane >> 2;
    const int tig  = lane & 3;
    const int r32  = (wid >> 1) * 32;
    const int c32  = (wid & 1) * 32;
    const int rowBase = blockIdx.y * 128;
    const int colBase = blockIdx.x * 64;

    const float* aPtr[4];
    int aR[4], aC[4];
    #pragma unroll
    for (int it = 0; it < 4; it++) {
        int e  = tid + it * 256;
        aR[it] = e >> 3;
        aC[it] = (e & 7) * 4;
        int m  = rowBase + aR[it];
        aPtr[it] = (m < rowSplit) ? (A1 + (size_t)m * K)
                                  : (A2 + (size_t)(m - rowSplit) * K);
    }
    const float* bPtr[2];
    int bR[2], bC[2];
    #pragma unroll
    for (int it = 0; it < 2; it++) {
        int e  = tid + it * 256;
        bR[it] = e >> 4;
        bC[it] = (e & 15) * 4;
        bPtr[it] = B + (size_t)bR[it] * N + colBase + bC[it];
    }

    float acc[2][4][4];
    #pragma unroll
    for (int m = 0; m < 2; m++)
        #pragma unroll
        for (int n = 0; n < 4; n++)
            #pragma unroll
            for (int r = 0; r < 4; r++) acc[m][n][r] = 0.f;

    const int nChunks = K >> 5;
    uint4 aReg[4], bReg[2];

    #pragma unroll
    for (int it = 0; it < 4; it++) aReg[it] = *(const uint4*)&aPtr[it][aC[it]];
    #pragma unroll
    for (int it = 0; it < 2; it++) bReg[it] = *(const uint4*)&bPtr[it][0];
    #pragma unroll
    for (int it = 0; it < 4; it++) *(uint4*)&As[0][aR[it]][aC[it]] = cvt4(aReg[it]);
    #pragma unroll
    for (int it = 0; it < 2; it++) *(uint4*)&Bs[0][bR[it]][bC[it]] = cvt4(bReg[it]);

    for (int c = 0; c < nChunks; c++) {
        const int cur = c & 1;
        __syncthreads();
        if (c + 1 < nChunks) {
            int k0 = (c + 1) << 5;
            #pragma unroll
            for (int it = 0; it < 4; it++) aReg[it] = *(const uint4*)&aPtr[it][k0 + aC[it]];
            #pragma unroll
            for (int it = 0; it < 2; it++) bReg[it] = *(const uint4*)&bPtr[it][(size_t)k0 * N];
        }

        #pragma unroll
        for (int ks = 0; ks < 4; ks++) {
            uint32_t af[2][4];
            #pragma unroll
            for (int m = 0; m < 2; m++) {
                int rb = r32 + m * 16;
                af[m][0] = As[cur][rb + gid][ks * 8 + tig];
                af[m][1] = As[cur][rb + gid + 8][ks * 8 + tig];
                af[m][2] = As[cur][rb + gid][ks * 8 + tig + 4];
                af[m][3] = As[cur][rb + gid + 8][ks * 8 + tig + 4];
            }
            #pragma unroll
            for (int n = 0; n < 4; n++) {
                uint32_t bf[2];
                bf[0] = Bs[cur][ks * 8 + tig][c32 + n * 8 + gid];
                bf[1] = Bs[cur][ks * 8 + tig + 4][c32 + n * 8 + gid];
                mma_tf32(acc[0][n], af[0], bf, acc[0][n]);
                mma_tf32(acc[1][n], af[1], bf, acc[1][n]);
            }
        }

        if (c + 1 < nChunks) {
            const int nxt = cur ^ 1;
            #pragma unroll
            for (int it = 0; it < 4; it++) *(uint4*)&As[nxt][aR[it]][aC[it]] = cvt4(aReg[it]);
            #pragma unroll
            for (int it = 0; it < 2; it++) *(uint4*)&Bs[nxt][bR[it]][bC[it]] = cvt4(bReg[it]);
        }
    }

    #pragma unroll
    for (int m = 0; m < 2; m++) {
        const size_t rlo = (size_t)(rowBase + r32 + m * 16 + gid) * N;
        const size_t rhi = (size_t)(rowBase + r32 + m * 16 + gid + 8) * N;
        #pragma unroll
        for (int n = 0; n < 4; n++) {
            int col = colBase + c32 + n * 8 + 2 * tig;
            float b0 = bias ? bias[col]     : 0.f;
            float b1 = bias ? bias[col + 1] : 0.f;
            *(float2*)&C[rlo + col] = make_float2(acc[m][n][0] + b0, acc[m][n][1] + b1);
            *(float2*)&C[rhi + col] = make_float2(acc[m][n][2] + b0, acc[m][n][3] + b1);
        }
    }
}

// ============ merged SR conv (x + y), tf32 MMA, double-buffered ============
__global__ void __launch_bounds__(256) mma_conv_kernel(
    const float* __restrict__ X1, const float* __restrict__ X2,
    const float* __restrict__ WT, const float* __restrict__ bias,
    float* __restrict__ C)
{
    __shared__ uint32_t As[2][64][ASTR];
    __shared__ uint32_t Bs[2][32][BSTR];

    const int tid  = threadIdx.x;
    const int wid  = tid >> 5;
    const int lane = tid & 31;
    const int gid  = lane >> 2;
    const int tig  = lane & 3;
    const int w16  = (wid >> 1) * 16;
    const int c32  = (wid & 1) * 32;
    const int rowBase = blockIdx.y * 64;
    const int colBase = blockIdx.x * 64;

    const float* aPtr[2];
    int aR[2], aSc[2], aIq[2];
    #pragma unroll
    for (int it = 0; it < 2; it++) {
        int e   = tid + it * 256;
        int r   = e >> 3;
        int sub = e & 7;
        int p   = sub & 3;
        int iq  = sub >> 2;
        int kh  = p >> 1, kw = p & 1;
        int m   = rowBase + r;
        const float* src;
        int mm, srcW;
        if (m < NRX) { src = X1; mm = m; srcW = 80; }
        else {
            int t = m - NRX;
            src = X2 + (size_t)(t / NRY) * NY * 256;
            mm  = t % NRY;
            srcW = 32;
        }
        int redW = srcW >> 1;
        int oh = mm / redW, ow = mm % redW;
        int tok = (oh * 2 + kh) * srcW + (ow * 2 + kw);
        aPtr[it] = src + (size_t)tok * 256;
        aR[it]  = r;
        aSc[it] = iq * 16 + p;
        aIq[it] = iq * 4;
    }
    const float* bPtr[2];
    int bR[2], bC[2];
    #pragma unroll
    for (int it = 0; it < 2; it++) {
        int e  = tid + it * 256;
        bR[it] = e >> 4;
        bC[it] = (e & 15) * 4;
        bPtr[it] = WT + (size_t)bR[it] * 256 + colBase + bC[it];
    }

    float acc[4][4];
    #pragma unroll
    for (int n = 0; n < 4; n++)
        #pragma unroll
        for (int r = 0; r < 4; r++) acc[n][r] = 0.f;

    const int nChunks = 32;
    float4 aReg[2];
    uint4  bReg[2];

    #pragma unroll
    for (int it = 0; it < 2; it++) {
        aReg[it] = *(const float4*)&aPtr[it][aIq[it]];
        bReg[it] = *(const uint4*)&bPtr[it][0];
    }
    #pragma unroll
    for (int it = 0; it < 2; it++) {
        int sc = aSc[it];
        As[0][aR[it]][sc + 0]  = to_tf32(aReg[it].x);
        As[0][aR[it]][sc + 4]  = to_tf32(aReg[it].y);
        As[0][aR[it]][sc + 8]  = to_tf32(aReg[it].z);
        As[0][aR[it]][sc + 12] = to_tf32(aReg[it].w);
        *(uint4*)&Bs[0][bR[it]][bC[it]] = cvt4(bReg[it]);
    }

    for (int c = 0; c < nChunks; c++) {
        const int cur = c & 1;
        __syncthreads();
        if (c + 1 < nChunks) {
            int i0 = ((c + 1) << 3);
            #pragma unroll
            for (int it = 0; it < 2; it++) {
                aReg[it] = *(const float4*)&aPtr[it][i0 + aIq[it]];
                bReg[it] = *(const uint4*)&bPtr[it][(size_t)((c + 1) << 5) * 256];
            }
        }

        #pragma unroll
        for (int ks = 0; ks < 4; ks++) {
            uint32_t af[4];
            af[0] = As[cur][w16 + gid][ks * 8 + tig];
            af[1] = As[cur][w16 + gid + 8][ks * 8 + tig];
            af[2] = As[cur][w16 + gid][ks * 8 + tig + 4];
            af[3] = As[cur][w16 + gid + 8][ks * 8 + tig + 4];
            #pragma unroll
            for (int n = 0; n < 4; n++) {
                uint32_t bf[2];
                bf[0] = Bs[cur][ks * 8 + tig][c32 + n * 8 + gid];
                bf[1] = Bs[cur][ks * 8 + tig + 4][c32 + n * 8 + gid];
                mma_tf32(acc[n], af, bf, acc[n]);
            }
        }

        if (c + 1 < nChunks) {
            const int nxt = cur ^ 1;
            #pragma unroll
            for (int it = 0; it < 2; it++) {
                int sc = aSc[it];
                As[nxt][aR[it]][sc + 0]  = to_tf32(aReg[it].x);
                As[nxt][aR[it]][sc + 4]  = to_tf32(aReg[it].y);
                As[nxt][aR[it]][sc + 8]  = to_tf32(aReg[it].z);
                As[nxt][aR[it]][sc + 12] = to_tf32(aReg[it].w);
                *(uint4*)&Bs[nxt][bR[it]][bC[it]] = cvt4(bReg[it]);
            }
        }
    }

    const size_t rlo = (size_t)(rowBase + w16 + gid) * 256;
    const size_t rhi = (size_t)(rowBase + w16 + gid + 8) * 256;
    #pragma unroll
    for (int n = 0; n < 4; n++) {
        int col = colBase + c32 + n * 8 + 2 * tig;
        float b0 = bias[col];
        float b1 = bias[col + 1];
        *(float2*)&C[rlo + col] = make_float2(acc[n][0] + b0, acc[n][1] + b1);
        *(float2*)&C[rhi + col] = make_float2(acc[n][2] + b0, acc[n][3] + b1);
    }
}

// ---------------- LayerNorm (in place) ----------------
__global__ void ln_kernel(float* __restrict__ red, const float* __restrict__ g,
                          const float* __restrict__ b)
{
    const int t = blockIdx.x;
    const int c = threadIdx.x;
    __shared__ float sh[8];
    __shared__ float s_mean, s_rstd;

    float v = red[(size_t)t * 256 + c];

    float x = v;
    #pragma unroll
    for (int o = 16; o > 0; o >>= 1) x += __shfl_xor_sync(FULL, x, o);
    if ((c & 31) == 0) sh[c >> 5] = x;
    __syncthreads();
    if (c == 0) {
        float s = 0.f;
        #pragma unroll
        for (int i = 0; i < 8; i++) s += sh[i];
        s_mean = s * (1.0f / 256.0f);
    }
    __syncthreads();

    float d = v - s_mean;
    float x2 = d * d;
    #pragma unroll
    for (int o = 16; o > 0; o >>= 1) x2 += __shfl_xor_sync(FULL, x2, o);
    if ((c & 31) == 0) sh[c >> 5] = x2;
    __syncthreads();
    if (c == 0) {
        float s = 0.f;
        #pragma unroll
        for (int i = 0; i < 8; i++) s += sh[i];
        s_rstd = rsqrtf(s * (1.0f / 256.0f) + 1e-5f);
    }
    __syncthreads();

    red[(size_t)t * 256 + c] = d * s_rstd * g[c] + b[c];
}

// ---------------- batch mean of support KV (tf32-rounded output) ----------------
__global__ void meankv_kernel(const float* __restrict__ kvy, float* __restrict__ out)
{
    int idx = blockIdx.x * 256 + threadIdx.x;
    const int STRIDE = NRY * 2 * DIM;
    float v = 0.25f * (kvy[idx] + kvy[idx + STRIDE] + kvy[idx + 2 * STRIDE] + kvy[idx + 3 * STRIDE]);
    out[idx] = __uint_as_float(to_tf32(v));
}

// ---------------- tf32 MMA flash attention: 64-q tiles, key-split halves ----------------
// blockIdx.z = half (0: keys [0,896), 1: keys [896,1856)). Writes UNNORMALIZED o + l.
constexpr int KSTR = 36;
constexpr int VSTR = 40;
constexpr int PSTR = 68;
constexpr int ATTN_SMEM = (2 * 64 * KSTR + 2 * 64 * VSTR + 64 * PSTR) * 4;  // 56320 B

__global__ void __launch_bounds__(128) attn_mma_kernel(
    const float* __restrict__ q_all, const float* __restrict__ KV1,
    const float* __restrict__ kvy, const float* __restrict__ kvym,
    float* __restrict__ po, float* __restrict__ pl, int N1, int N2)
{
    extern __shared__ uint32_t dyn[];
    uint32_t* KsB = dyn;
    uint32_t* VsB = dyn + 2 * 64 * KSTR;
    uint32_t* Ps  = dyn + 2 * 64 * KSTR + 2 * 64 * VSTR;
    const uint32_t smemBase = (uint32_t)__cvta_generic_to_shared(dyn);

    const int h    = blockIdx.y;
    const int bx   = blockIdx.x;
    const int half = blockIdx.z;

    const float* Q;
    const float* KV2;
    int q0, tokBase;
    if (bx < XBLK) {
        Q = q_all; KV2 = kvym; q0 = bx * 64; tokBase = 0;
    } else {
        int t  = bx - XBLK;
        int bz = t >> 4;
        int qb = t & 15;
        tokBase = NX + bz * NY;
        Q = q_all + (size_t)tokBase * 256;
        KV2 = kvy + (size_t)bz * NRY * 512;
        q0 = qb * 64;
    }
    float* O = po + (size_t)half * MQ * 256 + (size_t)tokBase * 256;

    const int tid  = threadIdx.x;
    const int wid  = tid >> 5;
    const int lane = tid & 31;
    const int gid  = lane >> 2;
    const int tig  = lane & 3;
    const int w16  = wid * 16;

    int sK[8], sOff[8];
    uint32_t dOff[8];
    int dStr[8];
    #pragma unroll
    for (int it = 0; it < 8; it++) {
        int s   = tid + it * 128;
        int r   = (s & 511) >> 3;
        int d4  = (s & 7) * 4;
        sK[it]  = r;
        if (s < 512) {
            sOff[it] = h * 32 + d4;
            dOff[it] = smemBase + (r * KSTR + d4) * 4;
            dStr[it] = 64 * KSTR * 4;
        } else {
            sOff[it] = 256 + h * 32 + d4;
            dOff[it] = smemBase + (2 * 64 * KSTR + r * VSTR + d4) * 4;
            dStr[it] = 64 * VSTR * 4;
        }
    }

    uint32_t qf[4][4];
    {
        const size_t rlo = (size_t)(q0 + w16 + gid) * 256 + h * 32;
        const size_t rhi = (size_t)(q0 + w16 + gid + 8) * 256 + h * 32;
        #pragma unroll
        for (int ks = 0; ks < 4; ks++) {
            int k0 = ks * 8;
            qf[ks][0] = to_tf32(Q[rlo + k0 + tig]     * SCALE_L2E);
            qf[ks][1] = to_tf32(Q[rhi + k0 + tig]     * SCALE_L2E);
            qf[ks][2] = to_tf32(Q[rlo + k0 + tig + 4] * SCALE_L2E);
            qf[ks][3] = to_tf32(Q[rhi + k0 + tig + 4] * SCALE_L2E);
        }
    }

    float l_lo = 0.f, l_hi = 0.f;
    float o[4][4];
    #pragma unroll
    for (int n = 0; n < 4; n++)
        #pragma unroll
        for (int r = 0; r < 4; r++) o[n][r] = 0.f;

    const int begKey = half ? KMID : 0;
    const int endKey = half ? (N1 + N2) : KMID;

    // prologue
    #pragma unroll
    for (int it = 0; it < 8; it++) {
        int kg = begKey + sK[it];
        const float* base = (kg < N1) ? (KV1 + (size_t)kg * 512)
                                      : (KV2 + (size_t)(kg - N1) * 512);
        cp_async16(dOff[it], base + sOff[it]);
    }
    asm volatile("cp.async.commit_group;" ::: "memory");

    int c = 0;
    for (int c0 = begKey; c0 < endKey; c0 += 64, c++) {
        const int cur = c & 1;
        asm volatile("cp.async.wait_group 0;" ::: "memory");
        __syncthreads();

        if (c0 + 64 < endKey) {
            int cn = c0 + 64;
            const int nxt = cur ^ 1;
            #pragma unroll
            for (int it = 0; it < 8; it++) {
                int kg = cn + sK[it];
                const float* base = (kg < N1) ? (KV1 + (size_t)kg * 512)
                                              : (KV2 + (size_t)(kg - N1) * 512);
                cp_async16(dOff[it] + nxt * dStr[it], base + sOff[it]);
            }
            asm volatile("cp.async.commit_group;" ::: "memory");
        }

        const uint32_t* Kc = KsB + cur * 64 * KSTR;
        const uint32_t* Vc = VsB + cur * 64 * VSTR;

        float s[8][4];
        #pragma unroll
        for (int n = 0; n < 8; n++) {
            s[n][0] = s[n][1] = s[n][2] = s[n][3] = 0.f;
            #pragma unroll
            for (int ks = 0; ks < 4; ks++) {
                uint32_t b[2];
                b[0] = Kc[(n * 8 + gid) * KSTR + ks * 8 + tig];
                b[1] = Kc[(n * 8 + gid) * KSTR + ks * 8 + tig + 4];
                mma_tf32(s[n], qf[ks], b, s[n]);
            }
        }

        float rs_lo = 0.f, rs_hi = 0.f;
        #pragma unroll
        for (int n = 0; n < 8; n++) {
            s[n][0] = ex2(s[n][0]);
            s[n][1] = ex2(s[n][1]);
            s[n][2] = ex2(s[n][2]);
            s[n][3] = ex2(s[n][3]);
            rs_lo += s[n][0] + s[n][1];
            rs_hi += s[n][2] + s[n][3];
        }
        rs_lo += __shfl_xor_sync(FULL, rs_lo, 1);
        rs_lo += __shfl_xor_sync(FULL, rs_lo, 2);
        rs_hi += __shfl_xor_sync(FULL, rs_hi, 1);
        rs_hi += __shfl_xor_sync(FULL, rs_hi, 2);
        l_lo += rs_lo;
        l_hi += rs_hi;

        #pragma unroll
        for (int n = 0; n < 8; n++) {
            int col = n * 8 + 2 * tig;
            Ps[(w16 + gid) * PSTR + col]         = to_tf32(s[n][0]);
            Ps[(w16 + gid) * PSTR + col + 1]     = to_tf32(s[n][1]);
            Ps[(w16 + gid + 8) * PSTR + col]     = to_tf32(s[n][2]);
            Ps[(w16 + gid + 8) * PSTR + col + 1] = to_tf32(s[n][3]);
        }
        __syncwarp();

        #pragma unroll
        for (int ks = 0; ks < 8; ks++) {
            uint32_t af[4];
            af[0] = Ps[(w16 + gid) * PSTR + ks * 8 + tig];
            af[1] = Ps[(w16 + gid + 8) * PSTR + ks * 8 + tig];
            af[2] = Ps[(w16 + gid) * PSTR + ks * 8 + tig + 4];
            af[3] = Ps[(w16 + gid + 8) * PSTR + ks * 8 + tig + 4];
            #pragma unroll
            for (int nd = 0; nd < 4; nd++) {
                uint32_t b[2];
                b[0] = Vc[(ks * 8 + tig) * VSTR + nd * 8 + gid];
                b[1] = Vc[(ks * 8 + tig + 4) * VSTR + nd * 8 + gid];
                mma_tf32(o[nd], af, b, o[nd]);
            }
        }
    }

    // write unnormalized partials + denominators
    const size_t rlo = (size_t)(q0 + w16 + gid) * 256 + h * 32;
    const size_t rhi = (size_t)(q0 + w16 + gid + 8) * 256 + h * 32;
    #pragma unroll
    for (int nd = 0; nd < 4; nd++) {
        int col = nd * 8 + 2 * tig;
        O[rlo + col]     = o[nd][0];
        O[rlo + col + 1] = o[nd][1];
        O[rhi + col]     = o[nd][2];
        O[rhi + col + 1] = o[nd][3];
    }
    if (tig == 0) {
        size_t lb = (size_t)half * MQ * HEADS;
        pl[lb + (size_t)(tokBase + q0 + w16 + gid) * HEADS + h]     = l_lo;
        pl[lb + (size_t)(tokBase + q0 + w16 + gid + 8) * HEADS + h] = l_hi;
    }
}

// ---------------- combine partial halves: o = (o0 + o1) / (l0 + l1) ----------------
__global__ void combine_kernel(const float* __restrict__ po, const float* __restrict__ pl,
                               float* __restrict__ o)
{
    int idx = blockIdx.x * 256 + threadIdx.x;   // over MQ*256
    int t = idx >> 8;
    int h = (idx & 255) >> 5;
    float l = pl[(size_t)t * HEADS + h] + pl[(size_t)MQ * HEADS + (size_t)t * HEADS + h];
    o[idx] = (po[idx] + po[(size_t)MQ * 256 + idx]) * (1.f / l);
}

// ---------------- launch ----------------
extern "C" void kernel_launch(void* const* d_in, const int* in_sizes, int n_in,
                              void* d_out, int out_size)
{
    const float* x   = (const float*)d_in[0];
    const float* y   = (const float*)d_in[1];
    const float* Wq  = (const float*)d_in[2];
    const float* Wkv = (const float*)d_in[3];
    const float* srw = (const float*)d_in[4];
    const float* srb = (const float*)d_in[5];
    const float* lng = (const float*)d_in[6];
    const float* lnb = (const float*)d_in[7];
    const float* pw  = (const float*)d_in[8];
    const float* pb  = (const float*)d_in[9];
    float* out = (float*)d_out;

    float *q, *o, *red, *kv, *kvym, *srwT, *po, *pl;
    cudaGetSymbolAddress((void**)&q,    g_q);
    cudaGetSymbolAddress((void**)&o,    g_o);
    cudaGetSymbolAddress((void**)&red,  g_red);
    cudaGetSymbolAddress((void**)&kv,   g_kv);
    cudaGetSymbolAddress((void**)&kvym, g_kvym);
    cudaGetSymbolAddress((void**)&srwT, g_srwT);
    cudaGetSymbolAddress((void**)&po,   g_po);
    cudaGetSymbolAddress((void**)&pl,   g_pl);

    float* kvy = kv + (size_t)NRX * 512;

    constexpr int SMEM128 = (2 * 128 * ASTR + 2 * 32 * BSTR) * 4;   // 55296 B
    cudaFuncSetAttribute(mma_gemm128_kernel,
                         cudaFuncAttributeMaxDynamicSharedMemorySize, SMEM128);
    cudaFuncSetAttribute(attn_mma_kernel,
                         cudaFuncAttributeMaxDynamicSharedMemorySize, ATTN_SMEM);

    transpose_w_kernel<<<1024, 256>>>(srw, srwT);

    // Q projection (merged, 128-row tiles)
    mma_gemm128_kernel<<<dim3(DIM / 64, MQ / 128), 256, SMEM128>>>(
        x, y, NX, Wq, nullptr, q, MQ, DIM, DIM);

    // SR conv (merged) + LN
    mma_conv_kernel<<<dim3(DIM / 64, MR / 64), 256>>>(x, y, srwT, srb, red);
    ln_kernel<<<MR, 256>>>(red, lng, lnb);

    // KV projection (merged, output pre-rounded to tf32)
    mma_gemm_kernel<<<dim3(2 * DIM / 64, MR / 64), 256>>>(red, red, MR, Wkv, nullptr, kv, MR, 2 * DIM, DIM, 1);

    // batch-mean support KV (tf32-rounded)
    meankv_kernel<<<(NRY * 2 * DIM) / 256, 256>>>(kvy, kvym);

    // attention: key-split halves (grid 164 x 8 x 2), then combine
    attn_mma_kernel<<<dim3(XBLK + BY * YBLK, HEADS, 2), 128, ATTN_SMEM>>>(
        q, kv, kvy, kvym, po, pl, NRX, NRY);
    combine_kernel<<<MQ, 256>>>(po, pl, o);

    // output projection (merged, 128-row tiles) into d_out
    mma_gemm128_kernel<<<dim3(DIM / 64, MQ / 128), 256, SMEM128>>>(
        o, o, MQ, pw, pb, out, MQ, DIM, DIM);
}